// round 1
// baseline (speedup 1.0000x reference)
#include <cuda_runtime.h>
#include <stdint.h>

#define REP   640
#define ROWS  32
#define MAXM  32768
#define MAXOUT 2048

// -------- device-global scratch (no allocations allowed) --------
__device__ unsigned g_ab[MAXM];      // packed (a | b<<16)
__device__ float    g_cgv[MAXM];     // cg coefficient
__device__ int      g_rov[MAXM];     // output index per entry
__device__ uint2    g_csr[MAXM];     // CSR-sorted entries: {packed ab, cg bits}
__device__ int      g_cnt[MAXOUT];   // per-output entry counts
__device__ int      g_rowptr[MAXOUT + 1];
__device__ int      g_is64;          // 1 if index arrays are int64, 0 if int32

// -------- 1) dtype detect + zero counters (1 block) --------
// If repids are int64, every odd 32-bit word is a (zero) high half.
__global__ void k_detect(const unsigned* __restrict__ ro_raw, int M, int out_dim) {
    for (int i = threadIdx.x; i < out_dim; i += blockDim.x) g_cnt[i] = 0;
    unsigned v = 0;
    int lim = (M < 8192) ? M : 8192;
    for (int i = 1 + 2 * threadIdx.x; i < lim; i += 2 * blockDim.x) v |= ro_raw[i];
    __shared__ unsigned s[256];
    s[threadIdx.x] = v;
    __syncthreads();
    for (int off = 128; off > 0; off >>= 1) {
        if (threadIdx.x < off) s[threadIdx.x] |= s[threadIdx.x + off];
        __syncthreads();
    }
    if (threadIdx.x == 0) g_is64 = (s[0] == 0u) ? 1 : 0;
}

// -------- 2) pack indices + histogram --------
__global__ void k_pack(const void* __restrict__ r1, const void* __restrict__ r2,
                       const void* __restrict__ ro, const float* __restrict__ cg, int M) {
    int i = blockIdx.x * blockDim.x + threadIdx.x;
    if (i >= M) return;
    int a, b, o;
    if (g_is64) {
        a = (int)((const long long*)r1)[i];
        b = (int)((const long long*)r2)[i];
        o = (int)((const long long*)ro)[i];
    } else {
        a = ((const int*)r1)[i];
        b = ((const int*)r2)[i];
        o = ((const int*)ro)[i];
    }
    g_ab[i]  = (unsigned)a | ((unsigned)b << 16);
    g_cgv[i] = cg[i];
    g_rov[i] = o;
    atomicAdd(&g_cnt[o], 1);
}

// -------- 3) prefix sum over counts (1 block, out_dim <= 1024) --------
__global__ void k_prefix(int out_dim) {
    __shared__ int s[1024];
    int t = threadIdx.x;
    s[t] = (t < out_dim) ? g_cnt[t] : 0;
    __syncthreads();
    for (int off = 1; off < 1024; off <<= 1) {
        int v = (t >= off) ? s[t - off] : 0;
        __syncthreads();
        s[t] += v;
        __syncthreads();
    }
    if (t < out_dim) g_rowptr[t + 1] = s[t];
    if (t == 0)      g_rowptr[0] = 0;
}

// -------- 4) stable CSR build: one warp per output bin, ballot order --------
__global__ void k_build(int M, int out_dim) {
    int w    = (blockIdx.x * blockDim.x + threadIdx.x) >> 5;
    int lane = threadIdx.x & 31;
    if (w >= out_dim) return;
    int base = g_rowptr[w];
    int cnt  = 0;
    for (int i0 = 0; i0 < M; i0 += 32) {
        int i = i0 + lane;
        int v = (i < M) ? g_rov[i] : -1;
        unsigned mask = __ballot_sync(0xffffffffu, v == w);
        if (v == w) {
            int pos = base + cnt + __popc(mask & ((1u << lane) - 1u));
            g_csr[pos] = make_uint2(g_ab[i], __float_as_uint(g_cgv[i]));
        }
        cnt += __popc(mask);
    }
}

// -------- 5) main kernel: 32 rows/CTA, warp-per-output, CSR gather --------
__global__ __launch_bounds__(1024, 1)
void k_main(const float* __restrict__ x1, const float* __restrict__ x2,
            float* __restrict__ out, int N, int out_dim, int M, int csr_in_smem) {
    extern __shared__ float sm[];
    float* x1t = sm;                       // [REP][32] XOR-swizzled
    float* x2t = sm + REP * ROWS;
    float* stg = sm + 2 * REP * ROWS;      // [32][33] output staging
    uint2* csrs = (uint2*)(stg + ROWS * 33);

    int tid  = threadIdx.x;
    int lane = tid & 31;
    int w    = tid >> 5;
    int rowbase = blockIdx.x * ROWS;

    // transposed, swizzled load of the 32-row x tiles (conflict-free both sides)
    for (int idx = tid; idx < ROWS * REP; idx += blockDim.x) {
        int r = idx / REP;
        int c = idx - r * REP;
        int gr = rowbase + r;
        float v1 = 0.f, v2 = 0.f;
        if (gr < N) {
            v1 = x1[(size_t)gr * REP + c];
            v2 = x2[(size_t)gr * REP + c];
        }
        int sa = (c << 5) + (r ^ (c & 31));
        x1t[sa] = v1;
        x2t[sa] = v2;
    }
    if (csr_in_smem) {
        for (int i = tid; i < M; i += blockDim.x) csrs[i] = g_csr[i];
    }
    __syncthreads();

    const uint2* csr = csr_in_smem ? (const uint2*)csrs : (const uint2*)g_csr;

    for (int ph = 0; ph * 32 < out_dim; ++ph) {
        int o = ph * 32 + w;
        float acc = 0.f;
        if (o < out_dim) {
            int e0 = g_rowptr[o];
            int e1 = g_rowptr[o + 1];
            for (int e = e0; e < e1; ++e) {
                uint2 ent = csr[e];                 // warp-uniform broadcast
                float cgv = __uint_as_float(ent.y);
                int a = ent.x & 0xFFFF;
                int b = ent.x >> 16;
                float va = x1t[(a << 5) + (lane ^ (a & 31))];
                float vb = x2t[(b << 5) + (lane ^ (b & 31))];
                acc = fmaf(cgv * va, vb, acc);
            }
        }
        stg[w * 33 + lane] = acc;                   // [o'][row], conflict-free
        __syncthreads();
        // coalesced store: lane -> consecutive output columns
        int oo = ph * 32 + lane;
        int gr = rowbase + w;
        if (oo < out_dim && gr < N)
            out[(size_t)gr * out_dim + oo] = stg[lane * 33 + w];
        __syncthreads();
    }
}

// -------- launcher --------
extern "C" void kernel_launch(void* const* d_in, const int* in_sizes, int n_in,
                              void* d_out, int out_size) {
    const float* x1 = (const float*)d_in[0];
    const float* x2 = (const float*)d_in[1];
    const float* cg = (const float*)d_in[2];
    const void*  r1 = d_in[3];
    const void*  r2 = d_in[4];
    const void*  ro = d_in[5];

    int M = in_sizes[2];
    if (M > MAXM) M = MAXM;
    int N = in_sizes[0] / REP;
    int out_dim = out_size / N;
    if (out_dim > MAXOUT) out_dim = MAXOUT;

    k_detect<<<1, 256>>>((const unsigned*)ro, M, out_dim);
    k_pack  <<<(M + 255) / 256, 256>>>(r1, r2, ro, cg, M);
    k_prefix<<<1, 1024>>>(out_dim);
    k_build <<<(out_dim * 32 + 255) / 256, 256>>>(M, out_dim);

    int base_b = (2 * REP * ROWS + ROWS * 33) * (int)sizeof(float);
    int csr_b  = M * (int)sizeof(uint2);
    int csr_in_smem = (base_b + csr_b <= 227 * 1024) ? 1 : 0;
    int smem = base_b + (csr_in_smem ? csr_b : 0);

    cudaFuncSetAttribute(k_main, cudaFuncAttributeMaxDynamicSharedMemorySize, smem);
    k_main<<<(N + ROWS - 1) / ROWS, 1024, smem>>>(x1, x2, (float*)d_out,
                                                  N, out_dim, M, csr_in_smem);
}

// round 2
// speedup vs baseline: 1.5983x; 1.5983x over previous
#include <cuda_runtime.h>
#include <stdint.h>

#define REP     640
#define ROWS    32
#define NPH     20            // max phases -> supports out_dim <= 640
#define NKEY    (32 * NPH)    // 640
#define MAXM    32768
#define STRIDE  33            // padded smem tile stride (conflict-free both sides)
#define SSTRIDE 641           // staging stride (== 1 mod 32)

// -------- device-global scratch --------
__device__ unsigned g_abp[MAXM];     // packed (a*33 | (b*33)<<16)
__device__ float    g_cgv[MAXM];
__device__ int      g_key[MAXM];     // (o&31)*NPH + (o>>5)
__device__ int      g_pos[MAXM];     // rank within bin (atomic order)
__device__ uint2    g_csr[MAXM];     // bin-sorted: {packed addrs, cg bits}
__device__ int      g_cnt[NKEY];
__device__ int      g_rowptr[NKEY + 1];
__device__ int      g_is64;

// -------- 1) dtype detect + zero counters --------
__global__ void k_detect(const unsigned* __restrict__ ro_raw, int M) {
    for (int i = threadIdx.x; i < NKEY; i += blockDim.x) g_cnt[i] = 0;
    unsigned v = 0;
    int lim = (M < 8192) ? M : 8192;
    for (int i = 1 + 2 * threadIdx.x; i < lim; i += 2 * blockDim.x) v |= ro_raw[i];
    __shared__ unsigned s[256];
    s[threadIdx.x] = v;
    __syncthreads();
    for (int off = 128; off > 0; off >>= 1) {
        if (threadIdx.x < off) s[threadIdx.x] |= s[threadIdx.x + off];
        __syncthreads();
    }
    if (threadIdx.x == 0) g_is64 = (s[0] == 0u) ? 1 : 0;
}

// -------- 2) pack indices, key, rank --------
__global__ void k_pack(const void* __restrict__ r1, const void* __restrict__ r2,
                       const void* __restrict__ ro, const float* __restrict__ cg, int M) {
    int i = blockIdx.x * blockDim.x + threadIdx.x;
    if (i >= M) return;
    int a, b, o;
    if (g_is64) {
        a = (int)((const long long*)r1)[i];
        b = (int)((const long long*)r2)[i];
        o = (int)((const long long*)ro)[i];
    } else {
        a = ((const int*)r1)[i];
        b = ((const int*)r2)[i];
        o = ((const int*)ro)[i];
    }
    int key = (o & 31) * NPH + (o >> 5);
    g_abp[i] = (unsigned)(a * STRIDE) | ((unsigned)(b * STRIDE) << 16);
    g_cgv[i] = cg[i];
    g_key[i] = key;
    g_pos[i] = atomicAdd(&g_cnt[key], 1);
}

// -------- 3) prefix sum over NKEY counts (1 block) --------
__global__ void k_prefix() {
    __shared__ int s[1024];
    int t = threadIdx.x;
    s[t] = (t < NKEY) ? g_cnt[t] : 0;
    __syncthreads();
    for (int off = 1; off < 1024; off <<= 1) {
        int v = (t >= off) ? s[t - off] : 0;
        __syncthreads();
        s[t] += v;
        __syncthreads();
    }
    if (t < NKEY) g_rowptr[t + 1] = s[t];
    if (t == 0)   g_rowptr[0] = 0;
}

// -------- 4) O(M) scatter into CSR --------
__global__ void k_scatter(int M) {
    int i = blockIdx.x * blockDim.x + threadIdx.x;
    if (i >= M) return;
    int p = g_rowptr[g_key[i]] + g_pos[i];
    g_csr[p] = make_uint2(g_abp[i], __float_as_uint(g_cgv[i]));
}

// -------- 5) main: 32 rows/CTA, warp-per-(o mod 32), register accumulators --------
__global__ __launch_bounds__(1024, 1)
void k_main(const float* __restrict__ x1, const float* __restrict__ x2,
            float* __restrict__ out, int N, int out_dim, int M, int csr_in_smem) {
    extern __shared__ float sm[];
    float* x1t = sm;                       // [REP][STRIDE]
    float* x2t = sm + REP * STRIDE;
    uint2* csrs = (uint2*)(sm + 2 * REP * STRIDE);           // 8B-aligned
    int*   srow = (int*)(sm + 2 * REP * STRIDE + (csr_in_smem ? 2 * M : 0));

    int tid  = threadIdx.x;
    int lane = tid & 31;
    int w    = tid >> 5;
    int rowbase = blockIdx.x * ROWS;

    // load x tiles: contiguous 32-row block, float4 global reads, padded transpose
    if (rowbase + ROWS <= N) {
        const float4* x1v = (const float4*)(x1 + (size_t)rowbase * REP);
        const float4* x2v = (const float4*)(x2 + (size_t)rowbase * REP);
        for (int i4 = tid; i4 < ROWS * REP / 4; i4 += 1024) {
            int idx = i4 * 4;
            int r = idx / REP;
            int c = idx - r * REP;
            float4 v1 = x1v[i4];
            float4 v2 = x2v[i4];
            x1t[(c + 0) * STRIDE + r] = v1.x;
            x1t[(c + 1) * STRIDE + r] = v1.y;
            x1t[(c + 2) * STRIDE + r] = v1.z;
            x1t[(c + 3) * STRIDE + r] = v1.w;
            x2t[(c + 0) * STRIDE + r] = v2.x;
            x2t[(c + 1) * STRIDE + r] = v2.y;
            x2t[(c + 2) * STRIDE + r] = v2.z;
            x2t[(c + 3) * STRIDE + r] = v2.w;
        }
    } else {
        for (int idx = tid; idx < ROWS * REP; idx += 1024) {
            int r = idx / REP;
            int c = idx - r * REP;
            int gr = rowbase + r;
            float v1 = 0.f, v2 = 0.f;
            if (gr < N) {
                v1 = x1[(size_t)gr * REP + c];
                v2 = x2[(size_t)gr * REP + c];
            }
            x1t[c * STRIDE + r] = v1;
            x2t[c * STRIDE + r] = v2;
        }
    }
    if (csr_in_smem)
        for (int i = tid; i < M; i += 1024) csrs[i] = g_csr[i];
    for (int i = tid; i <= NKEY; i += 1024) srow[i] = g_rowptr[i];
    __syncthreads();

    const uint2* csr = csr_in_smem ? (const uint2*)csrs : (const uint2*)g_csr;

    float acc[NPH];
#pragma unroll
    for (int ph = 0; ph < NPH; ++ph) acc[ph] = 0.f;

    int e = srow[w * NPH];   // warp's entries are contiguous across its 20 segments
#pragma unroll
    for (int ph = 0; ph < NPH; ++ph) {
        int e1 = srow[w * NPH + ph + 1];
        float a = 0.f;
        for (; e < e1; ++e) {
            uint2 ent = csr[e];                       // warp-uniform LDS.64
            int a1 = (int)(ent.x & 0xffffu) + lane;   // a*33 + lane : conflict-free
            int a2 = (int)(ent.x >> 16) + lane;       // b*33 + lane
            a = fmaf(__uint_as_float(ent.y) * x1t[a1], x2t[a2], a);
        }
        acc[ph] = a;
    }
    __syncthreads();

    // stage outputs in (dead) x1t region, stride 641 => conflict-free writes
    float* stg = sm;
#pragma unroll
    for (int ph = 0; ph < NPH; ++ph) {
        int o = ph * 32 + w;
        if (o < out_dim) stg[lane * SSTRIDE + o] = acc[ph];
    }
    __syncthreads();

    // coalesced global stores
    for (int i = tid; i < ROWS * out_dim; i += 1024) {
        int r = i / out_dim;
        int c = i - r * out_dim;
        int gr = rowbase + r;
        if (gr < N) out[(size_t)gr * out_dim + c] = stg[r * SSTRIDE + c];
    }
}

// -------- launcher --------
extern "C" void kernel_launch(void* const* d_in, const int* in_sizes, int n_in,
                              void* d_out, int out_size) {
    const float* x1 = (const float*)d_in[0];
    const float* x2 = (const float*)d_in[1];
    const float* cg = (const float*)d_in[2];
    const void*  r1 = d_in[3];
    const void*  r2 = d_in[4];
    const void*  ro = d_in[5];

    int M = in_sizes[2];
    if (M > MAXM) M = MAXM;
    int N = in_sizes[0] / REP;
    int out_dim = out_size / N;

    k_detect <<<1, 256>>>((const unsigned*)ro, M);
    k_pack   <<<(M + 255) / 256, 256>>>(r1, r2, ro, cg, M);
    k_prefix <<<1, 1024>>>();
    k_scatter<<<(M + 255) / 256, 256>>>(M);

    int x_b    = 2 * REP * STRIDE * (int)sizeof(float);
    int srow_b = (NKEY + 1) * (int)sizeof(int);
    int csr_b  = M * (int)sizeof(uint2);
    int csr_in_smem = (x_b + srow_b + csr_b <= 227 * 1024) ? 1 : 0;
    int smem = x_b + srow_b + (csr_in_smem ? csr_b : 0);

    cudaFuncSetAttribute(k_main, cudaFuncAttributeMaxDynamicSharedMemorySize, smem);
    k_main<<<(N + ROWS - 1) / ROWS, 1024, smem>>>(x1, x2, (float*)d_out,
                                                  N, out_dim, M, csr_in_smem);
}